// round 2
// baseline (speedup 1.0000x reference)
#include <cuda_runtime.h>
#include <math.h>

// Problem constants (from reference): B=16384, A=50, D=256, alpha=0.2
constexpr int Bn = 16384;
constexpr int An = 50;
constexpr int Dn = 256;
constexpr float ALPHA = 0.2f;

constexpr int NTHREADS = 256;           // 8 warps
constexpr int ROWS = An + 1;            // 51: row 50 = entity dot (bias term)
// smem layout: tile[An*Dn] fp32, then e[64] (padded), then att[64] (padded)
constexpr int SMEM_TILE_FLOATS = An * Dn;            // 12800
constexpr int SMEM_FLOATS = SMEM_TILE_FLOATS + 64 + 64;
constexpr int SMEM_BYTES = SMEM_FLOATS * (int)sizeof(float);  // 51712

__global__ __launch_bounds__(NTHREADS, 4)
void struct_attention_kernel(const float* __restrict__ attrs,   // [B, A, D]
                             const float* __restrict__ ent,     // [B, D]
                             const float* __restrict__ avec,    // [2D, 1]
                             float* __restrict__ out)           // [B, D]
{
    extern __shared__ float smem[];
    float* tile  = smem;                        // An*Dn
    float* e_s   = smem + SMEM_TILE_FLOATS;     // 64 slots (uses 51)
    float* att_s = e_s + 64;                    // 64 slots (uses 50)

    const int b    = blockIdx.x;
    const int t    = threadIdx.x;
    const int w    = t >> 5;
    const int lane = t & 31;

    const float4* a4     = reinterpret_cast<const float4*>(avec);             // 128 float4: [0,64)=a_attr, [64,128)=a_ent
    const float4* attrs4 = reinterpret_cast<const float4*>(attrs) + (size_t)b * (An * (Dn / 4));
    const float4* ent4   = reinterpret_cast<const float4*>(ent)   + (size_t)b * (Dn / 4);
    float4* tile4        = reinterpret_cast<float4*>(tile);

    // a_attr coefficients for this lane's two float4 slots (same for every row)
    const float4 aa0 = __ldg(a4 + lane);
    const float4 aa1 = __ldg(a4 + 32 + lane);

    // ---- Pass 1: load attrs tile into SMEM + per-row dot products -------
    // Warp w handles rows a = w, w+8, ... (51 virtual rows; row 50 = entity).
    // 'a' is warp-uniform, so branches and shfl stay convergent.
    // 2 independent LDG.128 per iteration x 7 unrolled iters -> MLP ~= 14/warp.
#pragma unroll
    for (int k = 0; k < 7; k++) {
        const int a = w + 8 * k;
        if (a < ROWS) {
            float4 v0, v1, c0, c1;
            if (a == An) {
                // virtual entity row: dot(entity_emb[b], a_ent)
                v0 = __ldg(ent4 + lane);
                v1 = __ldg(ent4 + 32 + lane);
                c0 = __ldg(a4 + 64 + lane);
                c1 = __ldg(a4 + 96 + lane);
            } else {
                const float4* row = attrs4 + a * (Dn / 4);
                v0 = __ldg(row + lane);
                v1 = __ldg(row + 32 + lane);
                c0 = aa0;
                c1 = aa1;
            }
            float p = v0.x * c0.x + v0.y * c0.y + v0.z * c0.z + v0.w * c0.w
                    + v1.x * c1.x + v1.y * c1.y + v1.z * c1.z + v1.w * c1.w;
#pragma unroll
            for (int off = 16; off; off >>= 1)
                p += __shfl_xor_sync(0xffffffffu, p, off);

            if (a < An) {
                tile4[a * (Dn / 4) + lane]      = v0;
                tile4[a * (Dn / 4) + 32 + lane] = v1;
            }
            if (lane == 0) e_s[a] = p;
        }
    }
    __syncthreads();

    // ---- Softmax over 50 scores (single warp) ---------------------------
    if (w == 0) {
        const float bias = e_s[An];
        float e0 = (lane      < An) ? e_s[lane]      + bias : -INFINITY;
        float e1 = (lane + 32 < An) ? e_s[lane + 32] + bias : -INFINITY;
        // leaky_relu (-inf stays -inf: 0.2 * -inf = -inf)
        e0 = (e0 > 0.f) ? e0 : ALPHA * e0;
        e1 = (e1 > 0.f) ? e1 : ALPHA * e1;

        float m = fmaxf(e0, e1);
#pragma unroll
        for (int off = 16; off; off >>= 1)
            m = fmaxf(m, __shfl_xor_sync(0xffffffffu, m, off));

        float p0 = __expf(e0 - m);   // exp(-inf) = 0 for masked lanes
        float p1 = __expf(e1 - m);
        float s = p0 + p1;
#pragma unroll
        for (int off = 16; off; off >>= 1)
            s += __shfl_xor_sync(0xffffffffu, s, off);

        const float scale = (float)An / s;   // softmax * attr_num
        if (lane      < An) att_s[lane]      = p0 * scale;
        if (lane + 32 < An) att_s[lane + 32] = p1 * scale;
    }
    __syncthreads();

    // ---- Pass 2: out[b, d] = sum_a att[a] * tile[a, d] ------------------
    // Vectorized: threads 0..63 each own a float4 column group (16B);
    // consecutive threads hit consecutive 16B -> conflict-free LDS.128.
    if (t < Dn / 4) {
        float4 acc = make_float4(0.f, 0.f, 0.f, 0.f);
#pragma unroll
        for (int a = 0; a < An; a++) {
            const float att = att_s[a];                 // broadcast LDS
            const float4 v  = tile4[a * (Dn / 4) + t];  // LDS.128
            acc.x = fmaf(att, v.x, acc.x);
            acc.y = fmaf(att, v.y, acc.y);
            acc.z = fmaf(att, v.z, acc.z);
            acc.w = fmaf(att, v.w, acc.w);
        }
        reinterpret_cast<float4*>(out)[(size_t)b * (Dn / 4) + t] = acc;
    }
}

extern "C" void kernel_launch(void* const* d_in, const int* in_sizes, int n_in,
                              void* d_out, int out_size)
{
    const float* attrs = (const float*)d_in[0];   // [B, A, D] fp32
    const float* ent   = (const float*)d_in[1];   // [B, D]    fp32
    const float* avec  = (const float*)d_in[2];   // [2D, 1]   fp32
    float* out         = (float*)d_out;           // [B, D]    fp32

    // 51.7 KB dynamic smem (> 48 KB static limit); attribute set is
    // idempotent and not a stream op, so it is graph-capture safe.
    cudaFuncSetAttribute(struct_attention_kernel,
                         cudaFuncAttributeMaxDynamicSharedMemorySize, SMEM_BYTES);

    struct_attention_kernel<<<Bn, NTHREADS, SMEM_BYTES>>>(attrs, ent, avec, out);
}